// round 1
// baseline (speedup 1.0000x reference)
#include <cuda_runtime.h>
#include <cuda_bf16.h>
#include <stdint.h>

// Problem constants
#define BB  16
#define DD  256
#define HH  32
#define WW  32
#define NN  16384          // B*H*W
#define KK  8192
#define CHW (DD*HH*WW)     // 262144
#define HW  (HH*WW)        // 1024

#define MT  128            // rows per block tile
#define KT  128            // codes per tile
#define DC  32             // D chunk
#define EPITCH 136         // padded pitch for e smem (16B aligned, low conflicts)

// scratch (static device globals — no allocation allowed)
__device__ float g_z2[NN];
__device__ float g_e2[KK];
__device__ int   g_idx[NN];
__device__ float g_partial[512];

// ---------------------------------------------------------------------------
// z2[n] = sum_d z[b,d,s]^2   (n = b*1024 + s), sequential fp32 per thread
__global__ void __launch_bounds__(256) k_z2(const float* __restrict__ z, float* __restrict__ z2) {
    int n = blockIdx.x * 256 + threadIdx.x;
    int b = n >> 10, s = n & 1023;
    const float* p = z + (size_t)b * CHW + s;
    float sum = 0.f;
#pragma unroll 8
    for (int d = 0; d < DD; d++) {
        float v = p[d * HW];
        sum = fmaf(v, v, sum);
    }
    z2[n] = sum;
}

// e2[k] = sum_d e[k,d]^2 ; warp per k
__global__ void __launch_bounds__(256) k_e2(const float* __restrict__ emb, float* __restrict__ e2) {
    int warp = (blockIdx.x * 256 + threadIdx.x) >> 5;
    int lane = threadIdx.x & 31;
    const float* p = emb + (size_t)warp * DD;
    float sum = 0.f;
#pragma unroll
    for (int j = 0; j < DD / 32; j++) {
        float v = p[lane + 32 * j];
        sum = fmaf(v, v, sum);
    }
#pragma unroll
    for (int m = 16; m; m >>= 1) sum += __shfl_xor_sync(0xffffffffu, sum, m);
    if (lane == 0) e2[warp] = sum;
}

// ---------------------------------------------------------------------------
// Fused distance GEMM + argmin. One block per 128-row tile; loops all of K.
__global__ void __launch_bounds__(256) k_argmin(
    const float* __restrict__ z, const float* __restrict__ emb,
    const float* __restrict__ z2, const float* __restrict__ e2,
    int* __restrict__ out_idx)
{
    __shared__ float zs[DC][MT];
    __shared__ float es[DC][EPITCH];
    __shared__ float z2s[MT];
    __shared__ float e2s[KT];

    const int t  = threadIdx.x;
    const int tx = t & 15;
    const int ty = t >> 4;
    const int n0 = blockIdx.x * MT;
    const int b  = n0 >> 10, s0 = n0 & 1023;
    const float* zb = z + (size_t)b * CHW + s0;

    if (t < MT) z2s[t] = z2[n0 + t];

    float bestv[8];
    int   besti[8];
#pragma unroll
    for (int i = 0; i < 8; i++) { bestv[i] = 3.4e38f; besti[i] = 0; }

    for (int kt = 0; kt < KK; kt += KT) {
        __syncthreads();                       // protect e2s from prev-tile readers
        if (t < KT) e2s[t] = e2[kt + t];

        float acc[8][8];
#pragma unroll
        for (int i = 0; i < 8; i++)
#pragma unroll
            for (int j = 0; j < 8; j++) acc[i][j] = 0.f;

        for (int dc = 0; dc < DD; dc += DC) {
            __syncthreads();                   // protect smem from prev compute
            // load z tile: zs[d][n]  (global n-contiguous -> coalesced float4)
#pragma unroll
            for (int j = 0; j < 4; j++) {
                int flat = t + j * 256;        // 0..1023
                int d  = flat >> 5;
                int n4 = (flat & 31) << 2;
                float4 v = *(const float4*)(zb + (size_t)(dc + d) * HW + n4);
                *(float4*)&zs[d][n4] = v;
            }
            // load e tile transposed: es[d][k]
#pragma unroll
            for (int j = 0; j < 4; j++) {
                int flat = t + j * 256;        // 0..1023
                int k  = flat >> 3;
                int d4 = (flat & 7) << 2;
                float4 v = *(const float4*)(emb + (size_t)(kt + k) * DD + dc + d4);
                es[d4 + 0][k] = v.x;
                es[d4 + 1][k] = v.y;
                es[d4 + 2][k] = v.z;
                es[d4 + 3][k] = v.w;
            }
            __syncthreads();
#pragma unroll 4
            for (int d = 0; d < DC; d++) {
                float a[8], bw[8];
                *(float4*)(a)     = *(const float4*)&zs[d][ty * 4];
                *(float4*)(a + 4) = *(const float4*)&zs[d][64 + ty * 4];
                *(float4*)(bw)     = *(const float4*)&es[d][tx * 4];
                *(float4*)(bw + 4) = *(const float4*)&es[d][64 + tx * 4];
#pragma unroll
                for (int i = 0; i < 8; i++)
#pragma unroll
                    for (int j = 0; j < 8; j++)
                        acc[i][j] = fmaf(a[i], bw[j], acc[i][j]);
            }
        }
        // d = (z2 + e2) - 2*dot, single-rounded like the reference; strict < keeps first index
#pragma unroll
        for (int i = 0; i < 8; i++) {
            int r = (i < 4) ? (ty * 4 + i) : (64 + ty * 4 + (i - 4));
            float zz = z2s[r];
#pragma unroll
            for (int j = 0; j < 8; j++) {
                int c = (j < 4) ? (tx * 4 + j) : (64 + tx * 4 + (j - 4));
                float dv = fmaf(-2.0f, acc[i][j], zz + e2s[c]);
                if (dv < bestv[i]) { bestv[i] = dv; besti[i] = kt + c; }
            }
        }
    }

    // reduce (val, idx) across the 16 tx lanes sharing each row (half-warp shuffles)
#pragma unroll
    for (int i = 0; i < 8; i++) {
        float v = bestv[i];
        int  ix = besti[i];
#pragma unroll
        for (int m = 8; m; m >>= 1) {
            float ov = __shfl_xor_sync(0xffffffffu, v, m, 16);
            int   oi = __shfl_xor_sync(0xffffffffu, ix, m, 16);
            if (ov < v || (ov == v && oi < ix)) { v = ov; ix = oi; }
        }
        if (tx == 0) {
            int r = (i < 4) ? (ty * 4 + i) : (64 + ty * 4 + (i - 4));
            out_idx[n0 + r] = ix;
        }
    }
}

// ---------------------------------------------------------------------------
// Gather embeddings -> NCHW output, accumulate per-block sq-diff (deterministic)
__global__ void __launch_bounds__(256) k_quantize(
    const float* __restrict__ z, const float* __restrict__ emb,
    const int* __restrict__ idx, float* __restrict__ out, float* __restrict__ partial)
{
    int n0 = blockIdx.x * 32;
    int lane = threadIdx.x & 31;
    int w = threadIdx.x >> 5;            // 8 warps
    int n = n0 + lane;
    int b = n >> 10, s = n & 1023;
    const float* erow = emb + (size_t)idx[n] * DD;
    const float* zp = z + (size_t)b * CHW + s;
    float* op = out + (size_t)b * CHW + s;

    float sq = 0.f;
    for (int d = w; d < DD; d += 8) {
        float e  = erow[d];
        float zv = zp[d * HW];
        op[d * HW] = e;
        float diff = e - zv;
        sq = fmaf(diff, diff, sq);
    }
    __shared__ float red[256];
    red[threadIdx.x] = sq;
    __syncthreads();
#pragma unroll
    for (int st = 128; st; st >>= 1) {
        if (threadIdx.x < st) red[threadIdx.x] += red[threadIdx.x + st];
        __syncthreads();
    }
    if (threadIdx.x == 0) partial[blockIdx.x] = red[0];
}

// loss + indices-as-float epilogue (single block, deterministic)
__global__ void __launch_bounds__(256) k_finalize(
    const float* __restrict__ partial, const int* __restrict__ idx, float* __restrict__ out)
{
    __shared__ float red[256];
    red[threadIdx.x] = partial[threadIdx.x] + partial[threadIdx.x + 256];
    __syncthreads();
#pragma unroll
    for (int st = 128; st; st >>= 1) {
        if (threadIdx.x < st) red[threadIdx.x] += red[threadIdx.x + st];
        __syncthreads();
    }
    if (threadIdx.x == 0) {
        float m = red[0] / 4194304.0f;
        out[(size_t)BB * CHW] = fmaf(0.25f, m, m);   // q_loss + 0.25*e_loss
    }
    for (int n = threadIdx.x; n < NN; n += 256)
        out[(size_t)BB * CHW + 1 + n] = (float)idx[n];
}

// ---------------------------------------------------------------------------
extern "C" void kernel_launch(void* const* d_in, const int* in_sizes, int n_in,
                              void* d_out, int out_size)
{
    const float* z   = (const float*)d_in[0];
    const float* emb = (const float*)d_in[1];
    float* out = (float*)d_out;

    float* z2; cudaGetSymbolAddress((void**)&z2, g_z2);
    float* e2; cudaGetSymbolAddress((void**)&e2, g_e2);
    int*   idx; cudaGetSymbolAddress((void**)&idx, g_idx);
    float* part; cudaGetSymbolAddress((void**)&part, g_partial);

    k_z2<<<NN / 256, 256>>>(z, z2);
    k_e2<<<KK / 8 / 32 * 32 / 32, 256>>>(emb, e2);   // 8192 warps / 8 per block = 1024 blocks
    k_argmin<<<NN / MT, 256>>>(z, emb, z2, e2, idx);
    k_quantize<<<NN / 32, 256>>>(z, emb, idx, out, part);
    k_finalize<<<1, 256>>>(part, idx, out);
}

// round 4
// speedup vs baseline: 7.7674x; 7.7674x over previous
#include <cuda_runtime.h>
#include <cuda_bf16.h>
#include <stdint.h>

// Problem constants
#define BB  16
#define DD  256
#define HH  32
#define WW  32
#define NN  16384
#define KK  8192
#define CHW (DD*HH*WW)
#define HW  (HH*WW)

#define NCHUNK  128
#define NCHUNKS (KK/NCHUNK)    // 64
#define GSZ     16
#define NGRP    (KK/GSZ)       // 512
#define MARGIN  2.5e-4f

// ---------------- device scratch (static globals; no allocation) -----------
__device__ float          g_zt[NN*DD];       // transposed z fp32 [n][d]
__device__ __nv_bfloat16  g_zbf[NN*DD];      // bf16 [n][d]
__device__ __nv_bfloat16  g_ebf[KK*DD];      // bf16 [k][d]
__device__ float          g_z2[NN];
__device__ float          g_e2[KK];
__device__ float          g_gmin[(size_t)NN*NGRP];   // [row][group] approx min of (e2-2dot)
__device__ int            g_idx[NN];
__device__ float          g_partial[512];

// ---------------- warp MMA helpers -----------------------------------------
__device__ __forceinline__ uint32_t smem_u32(const void* p) {
    uint32_t a;
    asm("{ .reg .u64 t; cvta.to.shared.u64 t, %1; cvt.u32.u64 %0, t; }" : "=r"(a) : "l"(p));
    return a;
}
__device__ __forceinline__ void ldsm4(uint32_t* r, uint32_t addr) {
    asm volatile("ldmatrix.sync.aligned.m8n8.x4.shared.b16 {%0,%1,%2,%3}, [%4];"
                 : "=r"(r[0]), "=r"(r[1]), "=r"(r[2]), "=r"(r[3]) : "r"(addr));
}
__device__ __forceinline__ void ldsm2(uint32_t* r, uint32_t addr) {
    asm volatile("ldmatrix.sync.aligned.m8n8.x2.shared.b16 {%0,%1}, [%2];"
                 : "=r"(r[0]), "=r"(r[1]) : "r"(addr));
}
__device__ __forceinline__ void mma_bf16(float* c, const uint32_t* a, const uint32_t* b) {
    asm volatile("mma.sync.aligned.m16n8k16.row.col.f32.bf16.bf16.f32 "
                 "{%0,%1,%2,%3}, {%4,%5,%6,%7}, {%8,%9}, {%0,%1,%2,%3};"
                 : "+f"(c[0]), "+f"(c[1]), "+f"(c[2]), "+f"(c[3])
                 : "r"(a[0]), "r"(a[1]), "r"(a[2]), "r"(a[3]), "r"(b[0]), "r"(b[1]));
}

// ---------------- prep: transpose z + bf16 cast + z2 ------------------------
__global__ void __launch_bounds__(256) k_transpose(const float* __restrict__ z) {
    __shared__ float ts[256][33];
    int t = threadIdx.x, lane = t & 31, w = t >> 5;
    int n0 = blockIdx.x * 32;
    int b = n0 >> 10, s0 = n0 & 1023;
    const float* zp = z + (size_t)b * CHW + s0;
#pragma unroll 8
    for (int j = 0; j < 32; j++) {
        int d = j * 8 + w;
        ts[d][lane] = zp[(size_t)d * HW + lane];
    }
    __syncthreads();
#pragma unroll 8
    for (int j = 0; j < 32; j++) {
        float v = ts[t][j];
        size_t o = (size_t)(n0 + j) * DD + t;
        g_zt[o]  = v;
        g_zbf[o] = __float2bfloat16_rn(v);
    }
#pragma unroll
    for (int q = 0; q < 4; q++) {
        int nl = w * 4 + q;
        float s = 0.f;
#pragma unroll
        for (int jj = 0; jj < 8; jj++) { float v = ts[lane + 32 * jj][nl]; s = fmaf(v, v, s); }
#pragma unroll
        for (int m = 16; m; m >>= 1) s += __shfl_xor_sync(0xffffffffu, s, m);
        if (lane == 0) g_z2[n0 + nl] = s;
    }
}

// prep: bf16 cast of embeddings + e2
__global__ void __launch_bounds__(256) k_prep_e(const float* __restrict__ emb) {
    int k = blockIdx.x * 8 + (threadIdx.x >> 5);
    int lane = threadIdx.x & 31;
    const float* p = emb + (size_t)k * DD;
    float sum = 0.f;
#pragma unroll
    for (int j = 0; j < DD / 32; j++) {
        float v = p[lane + 32 * j];
        sum = fmaf(v, v, sum);
        g_ebf[(size_t)k * DD + lane + 32 * j] = __float2bfloat16_rn(v);
    }
#pragma unroll
    for (int m = 16; m; m >>= 1) sum += __shfl_xor_sync(0xffffffffu, sum, m);
    if (lane == 0) g_e2[k] = sum;
}

// ---------------- phase 1: bf16 HMMA GEMM + per-group min -------------------
// grid (128, 2): bx = 128-row tile, by = chunk half (32 chunks each)
__global__ void __launch_bounds__(256, 2) k_mma() {
    __shared__ __align__(1024) __nv_bfloat16 zs[128 * 64];
    __shared__ __align__(1024) __nv_bfloat16 es[128 * 64];

    int t = threadIdx.x, lane = t & 31, wid = t >> 5;
    int wm = wid >> 2, wn = wid & 3;          // 2x4 warp grid, warp tile 64x32
    int n0 = blockIdx.x * 128;
    uint32_t zb = smem_u32(zs), eb = smem_u32(es);
    const __nv_bfloat16* zg = g_zbf + (size_t)n0 * DD;

    int sub  = lane >> 3;
    int arow = wm * 64 + ((sub & 1) << 3) + (lane & 7);  // + mi*16
    int acoff = sub >> 1;                                // 0/1
    int brow = wn * 32 + (lane & 7);                     // + ni*8
    int bsub = (lane >> 3) & 1;

    for (int cc = 0; cc < 32; cc++) {
        int c = blockIdx.y * 32 + cc;
        const __nv_bfloat16* eg = g_ebf + (size_t)c * NCHUNK * DD;

        float acc[4][4][4];
#pragma unroll
        for (int mi = 0; mi < 4; mi++)
#pragma unroll
            for (int ni = 0; ni < 4; ni++)
#pragma unroll
                for (int q = 0; q < 4; q++) acc[mi][ni][q] = 0.f;

#pragma unroll 1
        for (int dc = 0; dc < 4; dc++) {
            __syncthreads();
            int d0 = dc * 64;
#pragma unroll
            for (int j = 0; j < 4; j++) {
                int f = t + j * 256;
                int r = f >> 3, ch = f & 7;
                uint32_t so = (uint32_t)(r * 128 + ((ch ^ (r & 7)) << 4));
                *(uint4*)((char*)zs + so) = *(const uint4*)(zg + (size_t)r * DD + d0 + ch * 8);
                *(uint4*)((char*)es + so) = *(const uint4*)(eg + (size_t)r * DD + d0 + ch * 8);
            }
            __syncthreads();
#pragma unroll
            for (int ks = 0; ks < 4; ks++) {
                uint32_t b[4][2];
#pragma unroll
                for (int ni = 0; ni < 4; ni++) {
                    int row = brow + ni * 8;
                    int ci  = ks * 2 + bsub;
                    ldsm2(b[ni], eb + (uint32_t)(row * 128 + ((ci ^ (row & 7)) << 4)));
                }
#pragma unroll
                for (int mi = 0; mi < 4; mi++) {
                    uint32_t a4[4];
                    int row = arow + mi * 16;
                    int ci  = ks * 2 + acoff;
                    ldsm4(a4, zb + (uint32_t)(row * 128 + ((ci ^ (row & 7)) << 4)));
#pragma unroll
                    for (int ni = 0; ni < 4; ni++)
                        mma_bf16(acc[mi][ni], a4, b[ni]);
                }
            }
        }
        // epilogue: per-row per-16-col-group min of (e2 - 2*dot)
        float e2r[8];
#pragma unroll
        for (int ni = 0; ni < 4; ni++)
#pragma unroll
            for (int h = 0; h < 2; h++)
                e2r[ni * 2 + h] = __ldg(&g_e2[c * NCHUNK + wn * 32 + ni * 8 + (lane & 3) * 2 + h]);
#pragma unroll
        for (int mi = 0; mi < 4; mi++)
#pragma unroll
            for (int rh = 0; rh < 2; rh++) {
                float mp0 = 3.4e38f, mp1 = 3.4e38f;
#pragma unroll
                for (int ni = 0; ni < 4; ni++)
#pragma unroll
                    for (int h = 0; h < 2; h++) {
                        float dv = fmaf(-2.f, acc[mi][ni][rh * 2 + h], e2r[ni * 2 + h]);
                        if (ni < 2) { if (dv < mp0) mp0 = dv; }
                        else        { if (dv < mp1) mp1 = dv; }
                    }
                mp0 = fminf(mp0, __shfl_xor_sync(0xffffffffu, mp0, 1));
                mp0 = fminf(mp0, __shfl_xor_sync(0xffffffffu, mp0, 2));
                mp1 = fminf(mp1, __shfl_xor_sync(0xffffffffu, mp1, 1));
                mp1 = fminf(mp1, __shfl_xor_sync(0xffffffffu, mp1, 2));
                if ((lane & 3) == 0) {
                    int row = n0 + wm * 64 + mi * 16 + rh * 8 + (lane >> 2);
                    size_t base = (size_t)row * NGRP + c * 8 + wn * 2;
                    g_gmin[base]     = mp0;
                    g_gmin[base + 1] = mp1;
                }
            }
    }
}

// ---------------- phase 2: exact fp32 rescore (warp per row) ----------------
__global__ void __launch_bounds__(256) k_rescore(const float* __restrict__ emb) {
    __shared__ __align__(16) float zsh[8][256];
    __shared__ float gsh[8][512];
    int wid = threadIdx.x >> 5, lane = threadIdx.x & 31;
    int row = blockIdx.x * 8 + wid;

    const float* zr = g_zt + (size_t)row * DD;
#pragma unroll
    for (int j = 0; j < 8; j++) zsh[wid][lane + 32 * j] = zr[lane + 32 * j];

    float lm = 3.4e38f;
    const float* gmr = g_gmin + (size_t)row * NGRP;
#pragma unroll
    for (int i = 0; i < 16; i++) {
        float v = gmr[lane + 32 * i];
        gsh[wid][lane + 32 * i] = v;
        lm = fminf(lm, v);
    }
#pragma unroll
    for (int m = 16; m; m >>= 1) lm = fminf(lm, __shfl_xor_sync(0xffffffffu, lm, m));
    float thr = lm + MARGIN;
    __syncwarp();

    float z2r = g_z2[row];
    float bestv = 3.4e38f;
    int besti = 0x7fffffff;
    const float4* s4 = (const float4*)zsh[wid];

    for (int g0 = 0; g0 < NGRP; g0 += 32) {
        unsigned mask = __ballot_sync(0xffffffffu, gsh[wid][g0 + lane] <= thr);
        while (mask) {
            int g = g0 + (__ffs(mask) - 1);
            mask &= mask - 1;
            float dv = 3.4e38f;
            int code = 0x7fffffff;
            if (lane < GSZ) {
                code = g * GSZ + lane;
                const float4* er = (const float4*)(emb + (size_t)code * DD);
                float dot = 0.f;
#pragma unroll 16
                for (int d4 = 0; d4 < DD / 4; d4++) {
                    float4 a = s4[d4], b = er[d4];
                    dot = fmaf(a.x, b.x, dot); dot = fmaf(a.y, b.y, dot);
                    dot = fmaf(a.z, b.z, dot); dot = fmaf(a.w, b.w, dot);
                }
                dv = fmaf(-2.f, dot, z2r + g_e2[code]);
            }
            if (dv < bestv || (dv == bestv && code < besti)) { bestv = dv; besti = code; }
        }
    }
#pragma unroll
    for (int m = 16; m; m >>= 1) {
        float ov = __shfl_xor_sync(0xffffffffu, bestv, m);
        int   oi = __shfl_xor_sync(0xffffffffu, besti, m);
        if (ov < bestv || (ov == bestv && oi < besti)) { bestv = ov; besti = oi; }
    }
    if (lane == 0) g_idx[row] = besti;
}

// ---------------- epilogue: gather + loss -----------------------------------
__global__ void __launch_bounds__(256) k_quantize(
    const float* __restrict__ z, const float* __restrict__ emb, float* __restrict__ out) {
    int n0 = blockIdx.x * 32;
    int lane = threadIdx.x & 31;
    int w = threadIdx.x >> 5;
    int n = n0 + lane;
    int b = n >> 10, s = n & 1023;
    const float* erow = emb + (size_t)g_idx[n] * DD;
    const float* zp = z + (size_t)b * CHW + s;
    float* op = out + (size_t)b * CHW + s;

    float sq = 0.f;
    for (int d = w; d < DD; d += 8) {
        float e  = erow[d];
        float zv = zp[(size_t)d * HW];
        op[(size_t)d * HW] = e;
        float diff = e - zv;
        sq = fmaf(diff, diff, sq);
    }
    __shared__ float red[256];
    red[threadIdx.x] = sq;
    __syncthreads();
#pragma unroll
    for (int st = 128; st; st >>= 1) {
        if (threadIdx.x < st) red[threadIdx.x] += red[threadIdx.x + st];
        __syncthreads();
    }
    if (threadIdx.x == 0) g_partial[blockIdx.x] = red[0];
}

__global__ void __launch_bounds__(256) k_finalize(float* __restrict__ out) {
    __shared__ float red[256];
    red[threadIdx.x] = g_partial[threadIdx.x] + g_partial[threadIdx.x + 256];
    __syncthreads();
#pragma unroll
    for (int st = 128; st; st >>= 1) {
        if (threadIdx.x < st) red[threadIdx.x] += red[threadIdx.x + st];
        __syncthreads();
    }
    if (threadIdx.x == 0) {
        float m = red[0] / 4194304.0f;
        out[(size_t)BB * CHW] = fmaf(0.25f, m, m);   // q_loss + 0.25*e_loss
    }
    for (int n = threadIdx.x; n < NN; n += 256)
        out[(size_t)BB * CHW + 1 + n] = (float)g_idx[n];
}

// ---------------------------------------------------------------------------
extern "C" void kernel_launch(void* const* d_in, const int* in_sizes, int n_in,
                              void* d_out, int out_size) {
    const float* z   = (const float*)d_in[0];
    const float* emb = (const float*)d_in[1];
    float* out = (float*)d_out;

    k_transpose<<<NN / 32, 256>>>(z);
    k_prep_e<<<KK / 8, 256>>>(emb);
    k_mma<<<dim3(NN / 128, 2), 256>>>();
    k_rescore<<<NN / 8, 256>>>(emb);
    k_quantize<<<NN / 32, 256>>>(z, emb, out);
    k_finalize<<<1, 256>>>(out);
}